// round 12
// baseline (speedup 1.0000x reference)
#include <cuda_runtime.h>

#define NB 256
#define NT 64
#define ND 2048
#define NT_HALF 32
#define THRESHOLD 0.99f
#define EPSILON 0.01f

// Partial accumulator for the t=[32,64) half. 2 MB static device scratch.
__device__ float g_partial[NB * ND];

// Fused kernel. grid = (4, NB, 2), block = 128 threads.
// Phase 1: every block computes the ACT weights for batch b via warp scan
//          (cheap, L2-resident inputs). Block (0, b, 0) also writes
//          weights + ponder_cost to gmem.
// Phase 2: block z accumulates t in [z*32, z*32+32) for its D-chunk.
//          z=0 -> final_out, z=1 -> g_partial (combined by second kernel).
__global__ void __launch_bounds__(128) act_fused_kernel(
        const float* __restrict__ halt_probs,
        const float* __restrict__ outputs,
        const float* __restrict__ step_weights,
        float* __restrict__ final_out,
        float* __restrict__ ponder_out,
        float* __restrict__ weights_out) {
    __shared__ float wsh[NT];
    const int b = blockIdx.y;
    const int z = blockIdx.z;
    const unsigned FULL = 0xffffffffu;

    if (threadIdx.x < 32) {
        const int lane = threadIdx.x;
        const float* p  = halt_probs   + (size_t)b * NT;
        const float* sw = step_weights + (size_t)b * NT;

        float a = p[lane];          // t = lane
        float c = p[lane + 32];     // t = lane + 32

        // Inclusive scan over 64 elements (two 32-lane halves).
        float sa = a;
        #pragma unroll
        for (int off = 1; off < 32; off <<= 1) {
            float v = __shfl_up_sync(FULL, sa, off);
            if (lane >= off) sa += v;
        }
        float tot_a = __shfl_sync(FULL, sa, 31);
        float sc = c;
        #pragma unroll
        for (int off = 1; off < 32; off <<= 1) {
            float v = __shfl_up_sync(FULL, sc, off);
            if (lane >= off) sc += v;
        }
        sc += tot_a;

        // First t with cumsum >= THRESHOLD (fallback T-1).
        unsigned m1 = __ballot_sync(FULL, sa >= THRESHOLD);
        unsigned m2 = __ballot_sync(FULL, sc >= THRESHOLD);
        int h;
        if (m1)      h = __ffs(m1) - 1;
        else if (m2) h = 32 + __ffs(m2) - 1;
        else         h = NT - 1;

        float cum_at, p_at;
        if (h < 32) {
            cum_at = __shfl_sync(FULL, sa, h);
            p_at   = __shfl_sync(FULL, a,  h);
        } else {
            cum_at = __shfl_sync(FULL, sc, h - 32);
            p_at   = __shfl_sync(FULL, c,  h - 32);
        }
        float remaining = 1.0f - cum_at + p_at;

        float sw_a = sw[lane], sw_c = sw[lane + 32];
        int t0 = lane, t1 = lane + 32;
        float w0 = (t0 < h) ? a : ((t0 == h) ? remaining : 0.0f);
        float w1 = (t1 < h) ? c : ((t1 == h) ? remaining : 0.0f);
        w0 *= sw_a;
        w1 *= sw_c;

        float s = w0 + w1;
        #pragma unroll
        for (int off = 16; off > 0; off >>= 1)
            s += __shfl_xor_sync(FULL, s, off);
        float inv = 1.0f / fmaxf(s, EPSILON);

        w0 *= inv;
        w1 *= inv;
        wsh[t0] = w0;
        wsh[t1] = w1;

        if (blockIdx.x == 0 && z == 0) {
            weights_out[(size_t)b * NT + t0] = w0;
            weights_out[(size_t)b * NT + t1] = w1;
            float pc = w0 * (float)(t0 + 1) + w1 * (float)(t1 + 1);
            #pragma unroll
            for (int off = 16; off > 0; off >>= 1)
                pc += __shfl_xor_sync(FULL, pc, off);
            if (lane == 0) ponder_out[b] = pc;
        }
    }
    __syncthreads();

    // Phase 2: thread owns one float4 lane of D; t-range [z*32, z*32+32).
    const int idx = blockIdx.x * blockDim.x + threadIdx.x;   // float4 index in D
    const int row4 = ND / 4;
    const int tbase = z * NT_HALF;
    const float4* src = (const float4*)(outputs + (size_t)b * NT * ND)
                        + (size_t)tbase * row4 + idx;

    float4 acc = make_float4(0.f, 0.f, 0.f, 0.f);
    #pragma unroll
    for (int tb = 0; tb < NT_HALF; tb += 8) {
        float4 v[8];
        #pragma unroll
        for (int i = 0; i < 8; i++)
            v[i] = __ldcs(src + (size_t)(tb + i) * row4);
        #pragma unroll
        for (int i = 0; i < 8; i++) {
            float wt = wsh[tbase + tb + i];
            acc.x = fmaf(wt, v[i].x, acc.x);
            acc.y = fmaf(wt, v[i].y, acc.y);
            acc.z = fmaf(wt, v[i].z, acc.z);
            acc.w = fmaf(wt, v[i].w, acc.w);
        }
    }

    float4* dst = (z == 0) ? (float4*)(final_out + (size_t)b * ND)
                           : (float4*)(g_partial + (size_t)b * ND);
    dst[idx] = acc;
}

// Combine: final_out += g_partial. 131072 float4s -> grid 512 x 256 threads.
__global__ void __launch_bounds__(256) act_combine_kernel(float* __restrict__ final_out) {
    int i = blockIdx.x * blockDim.x + threadIdx.x;
    float4* dst = (float4*)final_out;
    const float4* part = (const float4*)g_partial;
    float4 a = dst[i];
    float4 p = part[i];
    a.x += p.x; a.y += p.y; a.z += p.z; a.w += p.w;
    dst[i] = a;
}

extern "C" void kernel_launch(void* const* d_in, const int* in_sizes, int n_in,
                              void* d_out, int out_size) {
    const float* halt_probs   = (const float*)d_in[0];  // [B, T, 1]
    const float* outputs      = (const float*)d_in[1];  // [B, T, D]
    const float* step_weights = (const float*)d_in[2];  // [B, T]

    float* final_out   = (float*)d_out;                 // [B, D]
    float* ponder_out  = final_out + (size_t)NB * ND;   // [B]
    float* weights_out = ponder_out + NB;               // [B, T]

    dim3 grid(ND / (128 * 4), NB, 2);                   // (4, 256, 2)
    act_fused_kernel<<<grid, 128>>>(halt_probs, outputs, step_weights,
                                    final_out, ponder_out, weights_out);

    act_combine_kernel<<<(NB * ND / 4) / 256, 256>>>(final_out);
}